// round 2
// baseline (speedup 1.0000x reference)
#include <cuda_runtime.h>
#include <cuda_bf16.h>
#include <cstdint>

#define NX    512
#define NU    128
#define ND    64
#define BATCH 256
#define TT    256
#define NCTA  128

typedef unsigned long long ull;

// ---------------- device scratch (allocation-free) ----------------
__device__ float    g_R[NX * NX];   // R[k][j] = W_eff[j][k] (transposed effective W)
__device__ unsigned g_count = 0;    // grid barrier arrival counter
__device__ unsigned g_phase = 0;    // grid barrier phase (monotonic, wraps safely)

// ---------------- packed f32x2 helpers ----------------
__device__ __forceinline__ void ffma2f(ull& acc, float lo, float hi, ull w) {
    asm volatile("{\n\t"
                 ".reg .b64 xa;\n\t"
                 "mov.b64 xa, {%1, %2};\n\t"
                 "fma.rn.f32x2 %0, xa, %3, %0;\n\t"
                 "}"
                 : "+l"(acc) : "f"(lo), "f"(hi), "l"(w));
}
__device__ __forceinline__ void ffma2(ull& acc, ull a, ull b) {
    asm volatile("fma.rn.f32x2 %0, %1, %2, %0;" : "+l"(acc) : "l"(a), "l"(b));
}
__device__ __forceinline__ float hsum2(ull v) {
    float lo, hi;
    asm("mov.b64 {%0, %1}, %2;" : "=f"(lo), "=f"(hi) : "l"(v));
    return lo + hi;
}

// ---------------- kernel 1: W_eff prep ----------------
// R[k][j] = (1 - 0.1*sigmoid(A_scalar[k][j])) * softmax_row_k(A_weight)[j]
__global__ void __launch_bounds__(256) prep_kernel(const float* __restrict__ Aw,
                                                   const float* __restrict__ As) {
    int k = blockIdx.x;
    int tid = threadIdx.x;
    __shared__ float red[256];
    const float* row = Aw + (size_t)k * NX;
    float a0 = row[tid], a1 = row[tid + 256];
    red[tid] = fmaxf(a0, a1);
    __syncthreads();
    for (int s = 128; s > 0; s >>= 1) {
        if (tid < s) red[tid] = fmaxf(red[tid], red[tid + s]);
        __syncthreads();
    }
    float mx = red[0];
    __syncthreads();
    float e0 = expf(a0 - mx), e1 = expf(a1 - mx);
    red[tid] = e0 + e1;
    __syncthreads();
    for (int s = 128; s > 0; s >>= 1) {
        if (tid < s) red[tid] += red[tid + s];
        __syncthreads();
    }
    float inv = 1.0f / red[0];
    const float* srow = As + (size_t)k * NX;
    float z0 = srow[tid], z1 = srow[tid + 256];
    float s0 = 1.0f - 0.1f / (1.0f + expf(-z0));
    float s1 = 1.0f - 0.1f / (1.0f + expf(-z1));
    g_R[(size_t)k * NX + tid]       = s0 * e0 * inv;
    g_R[(size_t)k * NX + tid + 256] = s1 * e1 * inv;
}

// ---------------- kernel 2: injection GEMM (written into X in-place) ----------------
// X[m][n] = sum_u U[m][u]*Bw[n][u] + sum_d D[m][d]*Ew[n][d], m = t*BATCH+b
#define INJ_AS   68
#define INJ_WS   194
#define INJ_SMEM ((64 * INJ_AS + 64 * INJ_WS) * 4)

__global__ void __launch_bounds__(256) inj_kernel(
    const float* __restrict__ U, const float* __restrict__ D,
    const float* __restrict__ Bw, const float* __restrict__ Ew,
    float* __restrict__ X)
{
    extern __shared__ float sm[];
    float* A_s = sm;                 // [64][INJ_AS]  m-major, k contiguous
    float* W_s = sm + 64 * INJ_AS;   // [64][INJ_WS]  n-major, k contiguous (K=192)
    int tid = threadIdx.x;
    int n0  = blockIdx.x * 64;
    size_t m0 = (size_t)blockIdx.y * 64;

    for (int i = tid; i < 64 * 192; i += 256) {
        int n = i / 192, k = i - n * 192;
        float v = (k < 128) ? Bw[(size_t)(n0 + n) * NU + k]
                            : Ew[(size_t)(n0 + n) * ND + (k - 128)];
        W_s[n * INJ_WS + k] = v;
    }

    int tn = tid & 15, tm = tid >> 4;   // thread tile: 4 m-rows, 4 n-cols
    ull acc[16];
#pragma unroll
    for (int i = 0; i < 16; i++) acc[i] = 0ull;

    for (int kc = 0; kc < 3; kc++) {
        __syncthreads();
        const float* src; int stride;
        if (kc < 2) { src = U + m0 * NU + kc * 64; stride = NU; }
        else        { src = D + m0 * ND;           stride = ND; }
        for (int i = tid; i < 1024; i += 256) {    // 64x64 floats as float4
            int r = i >> 4, c = i & 15;
            *(float4*)(A_s + r * INJ_AS + c * 4) =
                *(const float4*)(src + (size_t)r * stride + c * 4);
        }
        __syncthreads();
#pragma unroll
        for (int kp = 0; kp < 32; kp++) {          // k-pairs
            ull a[4], w[4];
#pragma unroll
            for (int i = 0; i < 4; i++)
                a[i] = *(const ull*)(A_s + (tm * 4 + i) * INJ_AS + 2 * kp);
#pragma unroll
            for (int j = 0; j < 4; j++)
                w[j] = *(const ull*)(W_s + (tn + 16 * j) * INJ_WS + kc * 64 + 2 * kp);
#pragma unroll
            for (int i = 0; i < 4; i++)
#pragma unroll
                for (int j = 0; j < 4; j++)
                    ffma2(acc[i * 4 + j], a[i], w[j]);
        }
    }
#pragma unroll
    for (int i = 0; i < 4; i++) {
        size_t m = m0 + tm * 4 + i;
#pragma unroll
        for (int j = 0; j < 4; j++)
            X[m * NX + n0 + tn + 16 * j] = hsum2(acc[i * 4 + j]);
    }
}

// ---------------- kernel 3: persistent scan with grid barrier ----------------
// 128 CTAs = 16 batch-groups x 8 k-column-groups; W slice pinned in SMEM.
// SMEM: Wp[256 jpair][65 pad][float2 kk]  (133120 B) + x_s[16][512] f32 (32768 B)
#define SCAN_SMEM (256 * 65 * 8 + 16 * NX * 4)

__global__ void __launch_bounds__(256, 1) scan_kernel(
    const float* __restrict__ x0, float* __restrict__ X, float* __restrict__ Y)
{
    extern __shared__ float smf[];
    ull*    Wpu  = (ull*)smf;                       // [jp*65 + kk] packed (R[k][2jp],R[k][2jp+1])
    float*  x_sf = smf + (256 * 65 * 8) / 4;        // 16 rows x 512 floats
    float4* x_s4 = (float4*)x_sf;
    float*  red  = x_sf;                            // 4*16*64 floats, aliased (used post-compute)

    const int tid  = threadIdx.x;
    const int lane = tid & 31;
    const int warp = tid >> 5;
    const int wk   = warp & 1;        // k half
    const int wj   = warp >> 1;       // j quarter
    const int kl   = wk * 32 + lane;  // local k 0..63
    const int gj   = blockIdx.x & 7;  // k range [gj*64, gj*64+64)
    const int gb   = blockIdx.x >> 3; // b range [gb*16, gb*16+16)

    unsigned base_phase = 0;
    if (tid == 0) base_phase = atomicAdd(&g_phase, 0u);   // read BEFORE first arrive

    // ---- pin W slice: Wp[jp][kk] = (R[gj*64+kk][2jp], R[...][2jp+1]) ----
    for (int i = tid; i < 64 * 256; i += 256) {
        int kk = i >> 8, jp = i & 255;
        float2 v = *(const float2*)(g_R + (size_t)(gj * 64 + kk) * NX + 2 * jp);
        ((float2*)Wpu)[jp * 65 + kk] = v;
    }
    // ---- stage x0 rows ----
    for (int i = tid; i < 2048; i += 256) {
        int b = i >> 7, c = i & 127;
        x_s4[b * 128 + c] = *(const float4*)(x0 + (size_t)(gb * 16 + b) * NX + 4 * c);
    }
    __syncthreads();

    for (int t = 0; t < TT; t++) {
        // ---- compute: acc[b] over this warp's j-quarter, lane-k ----
        ull acc[16];
#pragma unroll
        for (int b = 0; b < 16; b++) acc[b] = 0ull;
        const int q0 = wj * 32;                 // float4 index range (32 per warp)
#pragma unroll 2
        for (int q = q0; q < q0 + 32; q++) {
            ull w0 = Wpu[(2 * q) * 65 + kl];
            ull w1 = Wpu[(2 * q + 1) * 65 + kl];
#pragma unroll
            for (int b = 0; b < 16; b++) {
                float4 xv = x_s4[b * 128 + q];  // warp-broadcast
                ffma2f(acc[b], xv.x, xv.y, w0);
                ffma2f(acc[b], xv.z, xv.w, w1);
            }
        }
        __syncthreads();                        // everyone done reading x_s
        // ---- partials into red (aliases x_s) ----
#pragma unroll
        for (int b = 0; b < 16; b++)
            red[(wj * 16 + b) * 64 + kl] = hsum2(acc[b]);
        __syncthreads();
        // ---- reduce 4 partials + add inj (already in X) + write X, Y ----
        float* Xt = X + ((size_t)t * BATCH + gb * 16) * NX + gj * 64;
        for (int o = tid; o < 1024; o += 256) {
            int b = o >> 6, kk = o & 63;
            float s = red[(0 * 16 + b) * 64 + kk] + red[(1 * 16 + b) * 64 + kk]
                    + red[(2 * 16 + b) * 64 + kk] + red[(3 * 16 + b) * 64 + kk];
            float* p = Xt + (size_t)b * NX + kk;
            float v;
            asm volatile("ld.global.cg.f32 %0, [%1];" : "=f"(v) : "l"(p));
            v += s;
            asm volatile("st.global.cg.f32 [%0], %1;" :: "l"(p), "f"(v));
            if (gj == 7 && kk == 63)
                Y[t * BATCH + gb * 16 + b] = v;
        }
        // ---- grid barrier ----
        __syncthreads();
        if (tid == 0) {
            __threadfence();
            unsigned old = atomicAdd(&g_count, 1u);
            if (old == NCTA - 1) {
                g_count = 0;
                __threadfence();
                atomicAdd(&g_phase, 1u);
            } else {
                unsigned target = (unsigned)(t + 1);
                while (atomicAdd(&g_phase, 0u) - base_phase < target)
                    __nanosleep(64);
            }
            __threadfence();
        }
        __syncthreads();
        // ---- stage x_s = X[t] rows for next step ----
        if (t + 1 < TT) {
            const float* src = X + ((size_t)t * BATCH + gb * 16) * NX;
            for (int i = tid; i < 2048; i += 256) {
                int b = i >> 7, c = i & 127;
                float4 v;
                asm volatile("ld.global.cg.v4.f32 {%0,%1,%2,%3}, [%4];"
                             : "=f"(v.x), "=f"(v.y), "=f"(v.z), "=f"(v.w)
                             : "l"(src + (size_t)b * NX + 4 * c));
                x_s4[b * 128 + c] = v;
            }
            __syncthreads();
        }
    }
}

// ---------------- launch ----------------
extern "C" void kernel_launch(void* const* d_in, const int* in_sizes, int n_in,
                              void* d_out, int out_size) {
    const float* x0 = (const float*)d_in[0];
    const float* U  = (const float*)d_in[1];
    const float* D  = (const float*)d_in[2];
    const float* Aw = (const float*)d_in[3];
    const float* As = (const float*)d_in[4];
    const float* Bw = (const float*)d_in[5];
    const float* Ew = (const float*)d_in[6];
    float* X = (float*)d_out;                              // [T][BATCH][NX]
    float* Y = X + (size_t)TT * BATCH * NX;                // [T][BATCH]

    cudaFuncSetAttribute(inj_kernel,  cudaFuncAttributeMaxDynamicSharedMemorySize, INJ_SMEM);
    cudaFuncSetAttribute(scan_kernel, cudaFuncAttributeMaxDynamicSharedMemorySize, SCAN_SMEM);

    prep_kernel<<<NX, 256>>>(Aw, As);
    inj_kernel<<<dim3(8, (TT * BATCH) / 64), 256, INJ_SMEM>>>(U, D, Bw, Ew, X);
    scan_kernel<<<NCTA, 256, SCAN_SMEM>>>(x0, X, Y);
}

// round 4
// speedup vs baseline: 1.3972x; 1.3972x over previous
#include <cuda_runtime.h>
#include <cuda_bf16.h>
#include <cstdint>

#define NX    512
#define NU    128
#define ND    64
#define BATCH 256
#define TT    256
#define NCTA  128

typedef unsigned long long ull;

// ---------------- device scratch (allocation-free) ----------------
__device__ float    g_R[NX * NX];       // R[k][j] = W_eff[j][k]
__device__ unsigned g_cnt[16 * 32];     // per-batch-group monotonic counters (128B apart)

// ---------------- helpers ----------------
__device__ __forceinline__ void ffma2(ull& acc, ull a, ull b) {
    asm volatile("fma.rn.f32x2 %0, %1, %2, %0;" : "+l"(acc) : "l"(a), "l"(b));
}
__device__ __forceinline__ float hsum2(ull v) {
    float lo, hi;
    asm("mov.b64 {%0, %1}, %2;" : "=f"(lo), "=f"(hi) : "l"(v));
    return lo + hi;
}
__device__ __forceinline__ float ld_cg_f32(const float* p) {
    float v; asm volatile("ld.global.cg.f32 %0, [%1];" : "=f"(v) : "l"(p)); return v;
}
__device__ __forceinline__ void st_cg_f32(float* p, float v) {
    asm volatile("st.global.cg.f32 [%0], %1;" :: "l"(p), "f"(v));
}
__device__ __forceinline__ float4 ld_cg_f4(const float* p) {
    float4 v;
    asm volatile("ld.global.cg.v4.f32 {%0,%1,%2,%3}, [%4];"
                 : "=f"(v.x), "=f"(v.y), "=f"(v.z), "=f"(v.w) : "l"(p));
    return v;
}

// ---------------- kernel 1: W_eff prep (+ barrier counter reset) ----------------
__global__ void __launch_bounds__(256) prep_kernel(const float* __restrict__ Aw,
                                                   const float* __restrict__ As) {
    int k = blockIdx.x;
    int tid = threadIdx.x;
    if (k == 0 && tid < 16) g_cnt[tid * 32] = 0;     // graph-replay-safe reset
    __shared__ float red[256];
    const float* row = Aw + (size_t)k * NX;
    float a0 = row[tid], a1 = row[tid + 256];
    red[tid] = fmaxf(a0, a1);
    __syncthreads();
    for (int s = 128; s > 0; s >>= 1) {
        if (tid < s) red[tid] = fmaxf(red[tid], red[tid + s]);
        __syncthreads();
    }
    float mx = red[0];
    __syncthreads();
    float e0 = expf(a0 - mx), e1 = expf(a1 - mx);
    red[tid] = e0 + e1;
    __syncthreads();
    for (int s = 128; s > 0; s >>= 1) {
        if (tid < s) red[tid] += red[tid + s];
        __syncthreads();
    }
    float inv = 1.0f / red[0];
    const float* srow = As + (size_t)k * NX;
    float z0 = srow[tid], z1 = srow[tid + 256];
    float s0 = 1.0f - 0.1f / (1.0f + expf(-z0));
    float s1 = 1.0f - 0.1f / (1.0f + expf(-z1));
    g_R[(size_t)k * NX + tid]       = s0 * e0 * inv;
    g_R[(size_t)k * NX + tid + 256] = s1 * e1 * inv;
}

// ---------------- kernel 2: injection GEMM (in-place into X) ----------------
#define INJ_AS   68
#define INJ_WS   194
#define INJ_SMEM ((64 * INJ_AS + 64 * INJ_WS) * 4)

__global__ void __launch_bounds__(256) inj_kernel(
    const float* __restrict__ U, const float* __restrict__ D,
    const float* __restrict__ Bw, const float* __restrict__ Ew,
    float* __restrict__ X)
{
    extern __shared__ float sm[];
    float* A_s = sm;
    float* W_s = sm + 64 * INJ_AS;
    int tid = threadIdx.x;
    int n0  = blockIdx.x * 64;
    size_t m0 = (size_t)blockIdx.y * 64;

    for (int i = tid; i < 64 * 192; i += 256) {
        int n = i / 192, k = i - n * 192;
        float v = (k < 128) ? Bw[(size_t)(n0 + n) * NU + k]
                            : Ew[(size_t)(n0 + n) * ND + (k - 128)];
        W_s[n * INJ_WS + k] = v;
    }

    int tn = tid & 15, tm = tid >> 4;
    ull acc[16];
#pragma unroll
    for (int i = 0; i < 16; i++) acc[i] = 0ull;

    for (int kc = 0; kc < 3; kc++) {
        __syncthreads();
        const float* src; int stride;
        if (kc < 2) { src = U + m0 * NU + kc * 64; stride = NU; }
        else        { src = D + m0 * ND;           stride = ND; }
        for (int i = tid; i < 1024; i += 256) {
            int r = i >> 4, c = i & 15;
            *(float4*)(A_s + r * INJ_AS + c * 4) =
                *(const float4*)(src + (size_t)r * stride + c * 4);
        }
        __syncthreads();
#pragma unroll
        for (int kp = 0; kp < 32; kp++) {
            ull a[4], w[4];
#pragma unroll
            for (int i = 0; i < 4; i++)
                a[i] = *(const ull*)(A_s + (tm * 4 + i) * INJ_AS + 2 * kp);
#pragma unroll
            for (int j = 0; j < 4; j++)
                w[j] = *(const ull*)(W_s + (tn + 16 * j) * INJ_WS + kc * 64 + 2 * kp);
#pragma unroll
            for (int i = 0; i < 4; i++)
#pragma unroll
                for (int j = 0; j < 4; j++)
                    ffma2(acc[i * 4 + j], a[i], w[j]);
        }
    }
#pragma unroll
    for (int i = 0; i < 4; i++) {
        size_t m = m0 + tm * 4 + i;
#pragma unroll
        for (int j = 0; j < 4; j++)
            X[m * NX + n0 + tn + 16 * j] = hsum2(acc[i * 4 + j]);
    }
}

// ---------------- kernel 3: persistent scan, per-group sync ----------------
// 128 CTAs = 16 batch-groups (16 b) x 8 k-groups (64 cols).
// SMEM: W [128 q][66 pad] ull2 (135168B) + x_s 16x512 f32 (32768B) + red 8x16x64 f32 (32768B)
#define W_BYTES   (128 * 66 * 16)
#define XS_BYTES  (16 * NX * 4)
#define SCAN_SMEM (W_BYTES + XS_BYTES + 8 * 16 * 64 * 4)

__global__ void __launch_bounds__(256, 1) scan_kernel(
    const float* __restrict__ x0, float* __restrict__ X, float* __restrict__ Y)
{
    extern __shared__ char smraw[];
    ulonglong2* Wsm   = (ulonglong2*)smraw;                    // [q*66 + k_local]
    float4*     x_s4  = (float4*)(smraw + W_BYTES);            // [b*128 + q]
    ulonglong2* x_su2 = (ulonglong2*)(smraw + W_BYTES);
    float*      red   = (float*)(smraw + W_BYTES + XS_BYTES);  // [w][b][k_local]

    const int tid  = threadIdx.x;
    const int lane = tid & 31;
    const int warp = tid >> 5;        // j-eighth: q in [warp*16, warp*16+16)
    const int gj   = blockIdx.x & 7;  // out cols [gj*64, gj*64+64)
    const int gb   = blockIdx.x >> 3; // batches  [gb*16, gb*16+16)
    unsigned* cnt  = &g_cnt[gb * 32];

    // pin W slice: Wsm[q*66+kk] = R[gj*64+kk][4q .. 4q+3] (two packed j-pairs)
    for (int i = tid; i < 64 * 128; i += 256) {
        int kk = i >> 7, q = i & 127;
        float4 v = *(const float4*)(g_R + (size_t)(gj * 64 + kk) * NX + 4 * q);
        ((float4*)Wsm)[q * 66 + kk] = v;
    }
    // stage x0
    for (int i = tid; i < 2048; i += 256) {
        int b = i >> 7, c = i & 127;
        x_s4[b * 128 + c] = *(const float4*)(x0 + (size_t)(gb * 16 + b) * NX + 4 * c);
    }
    __syncthreads();

#pragma unroll 1
    for (int t = 0; t < TT; t++) {
        // ---- compute: packed even/odd-j partial sums, k = lane / lane+32 ----
        ull accA[16], accB[16];
#pragma unroll
        for (int b = 0; b < 16; b++) { accA[b] = 0ull; accB[b] = 0ull; }
        const int q0 = warp * 16;
#pragma unroll 4
        for (int q = q0; q < q0 + 16; q++) {
            ulonglong2 wa = Wsm[q * 66 + lane];
            ulonglong2 wb = Wsm[q * 66 + lane + 32];
#pragma unroll
            for (int b = 0; b < 16; b++) {
                ulonglong2 xp = x_su2[b * 128 + q];    // warp-broadcast
                ffma2(accA[b], xp.x, wa.x);
                ffma2(accA[b], xp.y, wa.y);
                ffma2(accB[b], xp.x, wb.x);
                ffma2(accB[b], xp.y, wb.y);
            }
        }
        // ---- partials ----
#pragma unroll
        for (int b = 0; b < 16; b++) {
            red[(warp * 16 + b) * 64 + lane]      = hsum2(accA[b]);
            red[(warp * 16 + b) * 64 + lane + 32] = hsum2(accB[b]);
        }
        __syncthreads();
        // ---- reduce 8 warps + inj (RMW on X, batched loads), write X and Y ----
        float* Xt = X + ((size_t)t * BATCH + gb * 16) * NX + gj * 64;
        float inj_r[4];
#pragma unroll
        for (int r = 0; r < 4; r++) {
            int o = tid + 256 * r, b = o >> 6, kk = o & 63;
            inj_r[r] = ld_cg_f32(Xt + (size_t)b * NX + kk);
        }
#pragma unroll
        for (int r = 0; r < 4; r++) {
            int o = tid + 256 * r, b = o >> 6, kk = o & 63;
            float s = inj_r[r];
#pragma unroll
            for (int w = 0; w < 8; w++) s += red[(w * 16 + b) * 64 + kk];
            st_cg_f32(Xt + (size_t)b * NX + kk, s);
            if (gj == 7 && kk == 63)
                Y[(size_t)t * BATCH + gb * 16 + b] = s;
        }
        if (t == TT - 1) break;
        // ---- per-group barrier: canonical release/acquire ----
        __threadfence();               // release: ALL threads drain their stores
        __syncthreads();
        if (tid == 0) {
            atomicAdd(cnt, 1u);
            unsigned target = 8u * (unsigned)(t + 1);
            while (atomicAdd(cnt, 0u) < target) { }   // strong read poll
            __threadfence();           // acquire
        }
        __syncthreads();
        // ---- stage x_s = X[t] for next step ----
        const float* src = X + ((size_t)t * BATCH + gb * 16) * NX;
        for (int i = tid; i < 2048; i += 256) {
            int b = i >> 7, c = i & 127;
            x_s4[b * 128 + c] = ld_cg_f4(src + (size_t)b * NX + 4 * c);
        }
        __syncthreads();
    }
}

// ---------------- launch ----------------
extern "C" void kernel_launch(void* const* d_in, const int* in_sizes, int n_in,
                              void* d_out, int out_size) {
    const float* x0 = (const float*)d_in[0];
    const float* U  = (const float*)d_in[1];
    const float* D  = (const float*)d_in[2];
    const float* Aw = (const float*)d_in[3];
    const float* As = (const float*)d_in[4];
    const float* Bw = (const float*)d_in[5];
    const float* Ew = (const float*)d_in[6];
    float* X = (float*)d_out;                   // [T][BATCH][NX]
    float* Y = X + (size_t)TT * BATCH * NX;     // [T][BATCH]

    cudaFuncSetAttribute(inj_kernel,  cudaFuncAttributeMaxDynamicSharedMemorySize, INJ_SMEM);
    cudaFuncSetAttribute(scan_kernel, cudaFuncAttributeMaxDynamicSharedMemorySize, SCAN_SMEM);

    prep_kernel<<<NX, 256>>>(Aw, As);
    inj_kernel<<<dim3(8, (TT * BATCH) / 64), 256, INJ_SMEM>>>(U, D, Bw, Ew, X);
    scan_kernel<<<NCTA, 256, SCAN_SMEM>>>(x0, X, Y);
}